// round 2
// baseline (speedup 1.0000x reference)
#include <cuda_runtime.h>
#include <cstdint>

#define BATCH   256
#define TSTEPS  1000
#define LIN     30
#define NCH     16
#define KW      7
#define LO      24
#define JDIM    384      // NCH*LO
#define NOUT    35
#define OPAD    36       // padded outputs
#define GR      12       // j-groups per output
#define JT      32       // j's per FC thread (GR*JT == JDIM)
#define NTHREADS 448     // 14 warps: 384 conv/mem1 threads, 432 FC threads
#define CHUNK   50       // timesteps of x per smem chunk
#define NCHUNK  (TSTEPS / CHUNK)

__device__ __forceinline__ uint32_t smem_u32(const void* p) {
    return (uint32_t)__cvta_generic_to_shared(p);
}
__device__ __forceinline__ void cp_async8(uint32_t dst, const void* src) {
    asm volatile("cp.async.ca.shared.global [%0], [%1], 8;" :: "r"(dst), "l"(src));
}
__device__ __forceinline__ void cp_commit() { asm volatile("cp.async.commit_group;"); }
__device__ __forceinline__ void cp_wait1()  { asm volatile("cp.async.wait_group 1;" ::: "memory"); }
__device__ __forceinline__ void cp_wait0()  { asm volatile("cp.async.wait_group 0;" ::: "memory"); }

__global__ __launch_bounds__(NTHREADS, 2)
void snn_kernel(const float* __restrict__ x,
                const float* __restrict__ conv_w,
                const float* __restrict__ conv_b,
                const float* __restrict__ fc_w,
                const float* __restrict__ fc_b,
                float* __restrict__ out)
{
    __shared__ __align__(16) float xs[2][CHUNK * LIN];   // 12 KB, double buffered
    __shared__ __align__(16) float spk[JDIM];            // spike floats (1.5 KB)
    __shared__ float part[GR][40];                       // FC partials, padded rows

    const int b   = blockIdx.x;
    const int tid = threadIdx.x;

    // ---- conv setup: thread tid < 384 owns mem1[tid], tid = ch*24 + pos ----
    float wc[KW];
    float bc = 0.f, mem1 = 0.f;
    int pos = 0;
    if (tid < JDIM) {
        int ch = tid / LO;
        pos    = tid % LO;
        #pragma unroll
        for (int k = 0; k < KW; ++k) wc[k] = conv_w[ch * KW + k];
        bc = conv_b[ch];
    }

    // ---- FC setup: thread < 432 -> output o = tid%36, group r = tid/36 ----
    // owns weights fc_w[o][r*32 .. r*32+31], packed as 16 f32x2 registers.
    const bool fcth = (tid < GR * OPAD);
    const int  o    = tid % OPAD;
    const int  r    = tid / OPAD;
    unsigned long long w2[JT / 2];
    if (fcth) {
        #pragma unroll
        for (int k = 0; k < JT / 2; ++k) {
            float lo_ = 0.f, hi_ = 0.f;
            if (o < NOUT) {
                lo_ = fc_w[o * JDIM + r * JT + 2 * k];
                hi_ = fc_w[o * JDIM + r * JT + 2 * k + 1];
            }
            asm("mov.b64 %0, {%1,%2};" : "=l"(w2[k]) : "f"(lo_), "f"(hi_));
        }
    }
    float  bias2 = 0.f, mem2 = 0.f;
    double acc   = 0.0;
    if (tid < NOUT) bias2 = fc_b[tid];

    const float* xb = x + (size_t)b * TSTEPS * LIN;

    // ---- prefetch chunk 0 (1500 floats = 750 x 8B) ----
    {
        uint32_t sbase = smem_u32(&xs[0][0]);
        for (int i = tid; i < CHUNK * LIN / 2; i += NTHREADS)
            cp_async8(sbase + i * 8, xb + i * 2);
        cp_commit();
    }

    for (int chunk = 0; chunk < NCHUNK; ++chunk) {
        const int buf = chunk & 1;
        if (chunk + 1 < NCHUNK) {
            uint32_t sbase   = smem_u32(&xs[buf ^ 1][0]);
            const float* src = xb + (size_t)(chunk + 1) * CHUNK * LIN;
            for (int i = tid; i < CHUNK * LIN / 2; i += NTHREADS)
                cp_async8(sbase + i * 8, src + i * 2);
            cp_commit();
            cp_wait1();   // current chunk's copies complete
        } else {
            cp_wait0();
        }
        __syncthreads();

        const float* xrow = &xs[buf][0];

        for (int tc = 0; tc < CHUNK; ++tc) {
            // ---------- Phase A: conv + LIF1 + spike ----------
            if (tid < JDIM) {
                const float* xr = xrow + tc * LIN + pos;
                float s = __fmul_rn(xr[0], wc[0]);
                #pragma unroll
                for (int k = 1; k < KW; ++k) s = __fmaf_rn(xr[k], wc[k], s);
                float c1 = __fadd_rn(s, bc);                  // bias added after sum (ref order)
                float r1 = (mem1 > 1.0f) ? 1.0f : 0.0f;       // reset on PREVIOUS membrane
                mem1 = __fsub_rn(__fadd_rn(__fmul_rn(0.9f, mem1), c1), r1);
                spk[tid] = (mem1 > 1.0f) ? 1.0f : 0.0f;       // (mem1 - 1 > 0) equivalent in fp32
            }
            __syncthreads();

            // ---------- Phase B: FC partial dot (binary spikes x register weights) ----------
            if (fcth) {
                uint32_t sp = smem_u32(&spk[r * JT]);          // warp-uniform -> broadcast LDS
                unsigned long long a0 = 0ull, a1 = 0ull;
                #pragma unroll
                for (int k = 0; k < JT / 2; k += 2) {
                    unsigned long long s0, s1;
                    asm("ld.shared.v2.u64 {%0,%1}, [%2];"
                        : "=l"(s0), "=l"(s1) : "r"(sp + (uint32_t)(k * 8)));
                    asm("fma.rn.f32x2 %0, %1, %2, %3;" : "=l"(a0) : "l"(s0), "l"(w2[k]),     "l"(a0));
                    asm("fma.rn.f32x2 %0, %1, %2, %3;" : "=l"(a1) : "l"(s1), "l"(w2[k + 1]), "l"(a1));
                }
                float x0, x1, y0, y1;
                asm("mov.b64 {%0,%1}, %2;" : "=f"(x0), "=f"(x1) : "l"(a0));
                asm("mov.b64 {%0,%1}, %2;" : "=f"(y0), "=f"(y1) : "l"(a1));
                part[r][o] = (x0 + x1) + (y0 + y1);
            }
            __syncthreads();

            // ---------- Phase C: reduce 12 partials, LIF2, accumulate ----------
            // (ordered before next Phase B's overwrite of `part` by the next
            //  iteration's first __syncthreads — no third barrier needed)
            if (tid < NOUT) {
                float c2 = part[0][tid];
                #pragma unroll
                for (int rr = 1; rr < GR; ++rr) c2 += part[rr][tid];  // ascending j-blocks
                c2 = __fadd_rn(c2, bias2);
                float r2 = (mem2 > 1.0f) ? 1.0f : 0.0f;
                mem2 = __fsub_rn(__fadd_rn(__fmul_rn(0.9f, mem2), c2), r2);
                acc += (double)mem2;
            }
        }
    }

    if (tid < NOUT)
        out[b * NOUT + tid] = (float)(acc * (1.0 / (double)TSTEPS));
}

extern "C" void kernel_launch(void* const* d_in, const int* in_sizes, int n_in,
                              void* d_out, int out_size)
{
    const float* x      = (const float*)d_in[0];
    const float* conv_w = (const float*)d_in[1];
    const float* conv_b = (const float*)d_in[2];
    const float* fc_w   = (const float*)d_in[3];
    const float* fc_b   = (const float*)d_in[4];
    snn_kernel<<<BATCH, NTHREADS>>>(x, conv_w, conv_b, fc_w, fc_b, (float*)d_out);
}

// round 6
// speedup vs baseline: 1.1556x; 1.1556x over previous
#include <cuda_runtime.h>
#include <cstdint>

#define BATCH   256
#define TSTEPS  1000
#define LIN     30
#define NCH     16
#define KW      7
#define LO      24
#define JDIM    384      // NCH*LO
#define NOUT    35
#define OPAD    36       // padded outputs
#define GR      12       // j-groups per output
#define JT      32       // j's per FC thread (GR*JT == JDIM)
#define NTHREADS 448     // 14 warps: A on 0-383, B on 0-431, C on 384-418
#define CHUNK   50       // timesteps of x per smem chunk
#define NCHUNK  (TSTEPS / CHUNK)

__device__ __forceinline__ uint32_t smem_u32(const void* p) {
    return (uint32_t)__cvta_generic_to_shared(p);
}
__device__ __forceinline__ void cp_async8(uint32_t dst, const void* src) {
    asm volatile("cp.async.ca.shared.global [%0], [%1], 8;" :: "r"(dst), "l"(src));
}
__device__ __forceinline__ void cp_commit() { asm volatile("cp.async.commit_group;"); }
__device__ __forceinline__ void cp_wait1()  { asm volatile("cp.async.wait_group 1;" ::: "memory"); }
__device__ __forceinline__ void cp_wait0()  { asm volatile("cp.async.wait_group 0;" ::: "memory"); }

// One pipelined iteration: C(t-2), B(t-1), A(t); single barrier at the end.
// Parities: A writes spk[pa]; B reads spk[pa^1], writes part[pa^1];
//           C reads part[pa]   (pa = t & 1).
#define STEP(PA, XROW, DOA, DOB, DOC)                                          \
  {                                                                            \
    const int pa_ = (PA);                                                      \
    if ((DOC) && cTh) {                                                        \
      float c2 = part[pa_][0][cIdx];                                           \
      _Pragma("unroll")                                                        \
      for (int rr = 1; rr < GR; ++rr) c2 += part[pa_][rr][cIdx];               \
      c2 = __fadd_rn(c2, bias2);                                               \
      float r2 = (mem2 > 1.0f) ? 1.0f : 0.0f;                                  \
      mem2 = __fsub_rn(__fadd_rn(__fmul_rn(0.9f, mem2), c2), r2);              \
      acc += (double)mem2;                                                     \
    }                                                                          \
    if ((DOB) && fcth) {                                                       \
      uint32_t sp = spkAddr + (uint32_t)((pa_ ^ 1) * (JDIM * 4));              \
      unsigned long long a0 = 0ull, a1 = 0ull;                                 \
      _Pragma("unroll")                                                        \
      for (int k = 0; k < JT / 2; k += 2) {                                    \
        unsigned long long s0, s1;                                             \
        asm("ld.shared.v2.u64 {%0,%1}, [%2];"                                  \
            : "=l"(s0), "=l"(s1) : "r"(sp + (uint32_t)(k * 8)));               \
        asm("fma.rn.f32x2 %0, %1, %2, %3;"                                     \
            : "=l"(a0) : "l"(s0), "l"(w2[k]),     "l"(a0));                    \
        asm("fma.rn.f32x2 %0, %1, %2, %3;"                                     \
            : "=l"(a1) : "l"(s1), "l"(w2[k + 1]), "l"(a1));                    \
      }                                                                        \
      float x0_, x1_, y0_, y1_;                                                \
      asm("mov.b64 {%0,%1}, %2;" : "=f"(x0_), "=f"(x1_) : "l"(a0));            \
      asm("mov.b64 {%0,%1}, %2;" : "=f"(y0_), "=f"(y1_) : "l"(a1));            \
      part[pa_ ^ 1][r][o] = (x0_ + x1_) + (y0_ + y1_);                         \
    }                                                                          \
    if ((DOA) && tid < JDIM) {                                                 \
      const float* xr = (XROW) + pos;                                          \
      float s = __fmul_rn(xr[0], wc[0]);                                       \
      _Pragma("unroll")                                                        \
      for (int k = 1; k < KW; ++k) s = __fmaf_rn(xr[k], wc[k], s);             \
      float c1 = __fadd_rn(s, bc);                                             \
      float r1 = (mem1 > 1.0f) ? 1.0f : 0.0f;                                  \
      mem1 = __fsub_rn(__fadd_rn(__fmul_rn(0.9f, mem1), c1), r1);              \
      spk[pa_][tid] = (mem1 > 1.0f) ? 1.0f : 0.0f;                             \
    }                                                                          \
    __syncthreads();                                                           \
  }

__global__ __launch_bounds__(NTHREADS, 2)
void snn_kernel(const float* __restrict__ x,
                const float* __restrict__ conv_w,
                const float* __restrict__ conv_b,
                const float* __restrict__ fc_w,
                const float* __restrict__ fc_b,
                float* __restrict__ out)
{
    __shared__ __align__(16) float xs[2][CHUNK * LIN];   // 12 KB double-buffered x
    __shared__ __align__(16) float spk[2][JDIM];         // double-buffered spikes
    __shared__ float part[2][GR][40];                    // double-buffered FC partials

    const int b   = blockIdx.x;
    const int tid = threadIdx.x;

    // ---- Phase A state: thread tid < 384 owns mem1[tid], tid = ch*24 + pos ----
    float wc[KW];
    float bc = 0.f, mem1 = 0.f;
    int pos = 0;
    if (tid < JDIM) {
        int ch = tid / LO;
        pos    = tid % LO;
        #pragma unroll
        for (int k = 0; k < KW; ++k) wc[k] = conv_w[ch * KW + k];
        bc = conv_b[ch];
    }

    // ---- Phase B state: thread < 432 -> output o = tid%36, group r = tid/36 ----
    const bool fcth = (tid < GR * OPAD);
    const int  o    = tid % OPAD;
    const int  r    = tid / OPAD;
    unsigned long long w2[JT / 2];
    if (fcth) {
        #pragma unroll
        for (int k = 0; k < JT / 2; ++k) {
            float lo_ = 0.f, hi_ = 0.f;
            if (o < NOUT) {
                lo_ = fc_w[o * JDIM + r * JT + 2 * k];
                hi_ = fc_w[o * JDIM + r * JT + 2 * k + 1];
            }
            asm("mov.b64 %0, {%1,%2};" : "=l"(w2[k]) : "f"(lo_), "f"(hi_));
        }
    }
    const uint32_t spkAddr = smem_u32(&spk[0][r * JT]);

    // ---- Phase C state: threads 384..418 own output cIdx (warp-12, B-light) ----
    const bool cTh  = (tid >= JDIM) && (tid < JDIM + NOUT);
    const int  cIdx = tid - JDIM;
    float  bias2 = 0.f, mem2 = 0.f;
    double acc   = 0.0;
    if (cTh) bias2 = fc_b[cIdx];

    const float* xb = x + (size_t)b * TSTEPS * LIN;

    // ---- prefetch chunk 0 ----
    {
        uint32_t sbase = smem_u32(&xs[0][0]);
        for (int i = tid; i < CHUNK * LIN / 2; i += NTHREADS)
            cp_async8(sbase + i * 8, xb + i * 2);
        cp_commit();
    }

    for (int chunk = 0; chunk < NCHUNK; ++chunk) {
        const int buf = chunk & 1;
        if (chunk + 1 < NCHUNK) {
            uint32_t sbase   = smem_u32(&xs[buf ^ 1][0]);
            const float* src = xb + (size_t)(chunk + 1) * CHUNK * LIN;
            for (int i = tid; i < CHUNK * LIN / 2; i += NTHREADS)
                cp_async8(sbase + i * 8, src + i * 2);
            cp_commit();
            cp_wait1();
        } else {
            cp_wait0();
        }
        __syncthreads();

        const float* xrow = &xs[buf][0];
        if (chunk == 0) {
            // pipeline fill: B off at tc=0, C off at tc<2
            #pragma unroll 2
            for (int tc = 0; tc < CHUNK; ++tc)
                STEP(tc & 1, xrow + tc * LIN, true, tc >= 1, tc >= 2);
        } else {
            // steady state ((chunk*50 + tc) & 1 == tc & 1 since CHUNK is even)
            #pragma unroll 2
            for (int tc = 0; tc < CHUNK; ++tc)
                STEP(tc & 1, xrow + tc * LIN, true, true, true);
        }
    }

    // ---- pipeline drain: iteration t=1000 (B(999), C(998)), t=1001 (C(999)) ----
    STEP(0, (const float*)nullptr, false, true, true);
    STEP(1, (const float*)nullptr, false, false, true);

    if (cTh)
        out[b * NOUT + cIdx] = (float)(acc * (1.0 / (double)TSTEPS));
}

extern "C" void kernel_launch(void* const* d_in, const int* in_sizes, int n_in,
                              void* d_out, int out_size)
{
    const float* x      = (const float*)d_in[0];
    const float* conv_w = (const float*)d_in[1];
    const float* conv_b = (const float*)d_in[2];
    const float* fc_w   = (const float*)d_in[3];
    const float* fc_b   = (const float*)d_in[4];
    snn_kernel<<<BATCH, NTHREADS>>>(x, conv_w, conv_b, fc_w, fc_b, (float*)d_out);
}